// round 12
// baseline (speedup 1.0000x reference)
#include <cuda_runtime.h>
#include <math.h>

#define BB 16
#define NN 4096
#define MM 1024
#define NSPLIT 32
#define NTS (NN / NSPLIT)   // 128: skel tile size
#define MSPLIT 4
#define MTS (MM / MSPLIT)   // 256: shape tile size

#define KEY_MASK 0xFFFFFC00u
#define IDX_MASK 0x000003FFu

typedef unsigned long long u64;

// scratch (static device globals: no allocation allowed)
__device__ uint2        g_pk[BB * MM * NSPLIT];      // per-split (best, second) keys
__device__ float        g_sm[128 * MSPLIT * 512];    // shape quarter-tile partial tmins
__device__ float        g_ps[128];                   // shape-group partials (16*8)
__device__ float        g_pm[32];                    // merge-group partials (16*2)
__device__ unsigned int g_gc[32];                    // skel merge counters (wrap 31)
__device__ unsigned int g_sc[128];                   // shape combine counters (wrap 3)
__device__ unsigned int g_cnt = 0;                   // global counter (160 units)

// ---- packed f32x2 helpers ----
__device__ __forceinline__ u64 fmx2(u64 a, u64 b, u64 c) {
    u64 r; asm("fma.rn.f32x2 %0,%1,%2,%3;" : "=l"(r) : "l"(a), "l"(b), "l"(c)); return r;
}
__device__ __forceinline__ u64 pk2(float a, float b) {
    u64 r; asm("mov.b64 %0,{%1,%2};" : "=l"(r) : "f"(a), "f"(b)); return r;
}
__device__ __forceinline__ void upkf(u64 v, float& a, float& b) {
    asm("mov.b64 {%0,%1},%2;" : "=f"(a), "=f"(b) : "l"(v));
}

// branch-free top-2 update on packed keys (positive-float uint ordering)
__device__ __forceinline__ void upd2(unsigned& b1, unsigned& b2, unsigned k) {
    unsigned mx = max(k, b1);
    b2 = min(b2, mx);
    b1 = min(b1, k);
}
// float variant (correct IEEE order incl. negatives; no NaNs here)
__device__ __forceinline__ void upd2f(float& b1, float& b2, float k) {
    float mx = fmaxf(k, b1);
    b2 = fminf(b2, mx);
    b1 = fminf(b1, k);
}

__device__ __forceinline__ float blockSum128(float v) {
    #pragma unroll
    for (int o = 16; o; o >>= 1) v += __shfl_xor_sync(0xFFFFFFFFu, v, o);
    __shared__ float ws[4];
    int w = threadIdx.x >> 5, l = threadIdx.x & 31;
    if (l == 0) ws[w] = v;
    __syncthreads();
    if (threadIdx.x == 0) v = ws[0] + ws[1] + ws[2] + ws[3];
    return v;  // valid on thread 0
}

// final scalar reduction over all 160 partials (block-uniform call, 128 thr)
__device__ __forceinline__ void finalize(float* out) {
    double acc = (double)g_ps[threadIdx.x];
    if (threadIdx.x < 32) acc += (double)g_pm[threadIdx.x];
    #pragma unroll
    for (int o = 16; o; o >>= 1) acc += __shfl_xor_sync(0xFFFFFFFFu, acc, o);
    __shared__ double wd[4];
    if ((threadIdx.x & 31) == 0) wd[threadIdx.x >> 5] = acc;
    __syncthreads();
    if (threadIdx.x == 0) out[0] = (float)(wd[0] + wd[1] + wd[2] + wd[3]);
}

// ---------------------------------------------------------------------------
// Single fused kernel, 4 queries/thread.
//   blocks [0, 1024):    skel: 512 m's vs one 128-pt N-split (32 splits).
//                        Last split-block per (b,mchunk) merges + cd2/normals.
//   blocks [1024, 1536): shape: 512 n's vs one 256-pt M-quarter (4 quarters).
//                        Last quarter-block per (b,nchunk) combines -> cd1.
// grid = 1536, block = 128
// ---------------------------------------------------------------------------
__global__ void __launch_bounds__(128) k_all(const float* __restrict__ shape,
                                             const float* __restrict__ skel,
                                             const float* __restrict__ nori,
                                             float* __restrict__ out) {
    __shared__ __align__(16) float sx[256];
    __shared__ __align__(16) float sy[256];
    __shared__ __align__(16) float sz[256];
    __shared__ __align__(16) float sw[256];
    __shared__ __align__(16) float4 s4[128];   // AoS shadow for skel rescans
    __shared__ bool doFin, lastUnit;

    const int bid = blockIdx.x;
    const int tid = threadIdx.x;

    if (bid < 1024) {
        // ================= skel part (4 m-queries per thread) ================
        const int b      = bid >> 6;        // 16
        const int r      = bid & 63;
        const int split  = r & 31;          // 32
        const int mchunk = r >> 5;          // 2
        const int nbase  = split * NTS;
        const int grp    = b * 2 + mchunk;

        if (tid < NTS) {
            const float* p = shape + ((size_t)(b * NN + nbase + tid)) * 6;
            float X = p[0], Y = p[1], Z = p[2];
            float W = X * X + Y * Y + Z * Z;
            sx[tid] = X; sy[tid] = Y; sz[tid] = Z; sw[tid] = W;
            s4[tid] = make_float4(X, Y, Z, W);
        }
        __syncthreads();

        const int mbase = mchunk * 512 + tid;
        float ppq[4];
        u64 m2x[4], m2y[4], m2z[4];
        float c[4][4];
        #pragma unroll
        for (int qi = 0; qi < 4; qi++) {
            const int m = mbase + qi * 128;
            const float* s = skel + ((size_t)(b * MM + m)) * 3;
            float qx = s[0], qy = s[1], qz = s[2];
            ppq[qi] = qx * qx + qy * qy + qz * qz;
            m2x[qi] = pk2(-2.0f * qx, -2.0f * qx);
            m2y[qi] = pk2(-2.0f * qy, -2.0f * qy);
            m2z[qi] = pk2(-2.0f * qz, -2.0f * qz);
            #pragma unroll
            for (int i = 0; i < 4; i++) c[qi][i] = 1e30f;
        }

        const ulonglong2* x2 = (const ulonglong2*)sx;
        const ulonglong2* y2 = (const ulonglong2*)sy;
        const ulonglong2* z2 = (const ulonglong2*)sz;
        const ulonglong2* w2 = (const ulonglong2*)sw;

        // 4 chains track FLOAT minima of t = w - 2 p.s over pts == k (mod 4);
        // pp is a per-query constant, folded in after the loop.
        #pragma unroll 2
        for (int j = 0; j < NTS; j += 4) {
            const int g = j >> 2;
            ulonglong2 xa = x2[g], ya = y2[g], za = z2[g], wa = w2[g];

            #pragma unroll
            for (int qi = 0; qi < 4; qi++) {
                u64 q01 = fmx2(xa.x, m2x[qi], fmx2(ya.x, m2y[qi], fmx2(za.x, m2z[qi], wa.x)));
                u64 q23 = fmx2(xa.y, m2x[qi], fmx2(ya.y, m2y[qi], fmx2(za.y, m2z[qi], wa.y)));
                float f0, f1, f2, f3;
                upkf(q01, f0, f1);
                upkf(q23, f2, f3);
                c[qi][0] = fminf(c[qi][0], f0);
                c[qi][1] = fminf(c[qi][1], f1);
                c[qi][2] = fminf(c[qi][2], f2);
                c[qi][3] = fminf(c[qi][3], f3);
            }
        }

        #pragma unroll
        for (int qi = 0; qi < 4; qi++) {
            // top-2 float values over the 4 chain minima
            float t1v = 1e30f, t2v = 1e30f;
            #pragma unroll
            for (int i = 0; i < 4; i++) upd2f(t1v, t2v, c[qi][i]);
            const int t1b = __float_as_int(t1v);
            const int t2b = __float_as_int(t2v);

            // cc1 = lowest chain attaining t1; cc2 = lowest other chain at t2
            int cc1 = 3;
            #pragma unroll
            for (int k = 2; k >= 0; k--) if (__float_as_int(c[qi][k]) == t1b) cc1 = k;
            int cc2 = (cc1 == 0) ? 1 : 0;
            #pragma unroll
            for (int k = 3; k >= 0; k--) if (__float_as_int(c[qi][k]) == t2b && k != cc1) cc2 = k;

            const float pp = ppq[qi];
            float fx, fyv, fz, dum;
            upkf(m2x[qi], fx, dum);
            upkf(m2y[qi], fyv, dum);
            upkf(m2z[qi], fz, dum);

            // rescan chain cc1 (32 pts): exact quantized top-2 with indices
            // (identical scalar FMA sequence -> bit-identical values)
            unsigned k1c = ~0u, k2c = ~0u;
            #pragma unroll 4
            for (int j = cc1; j < NTS; j += 4) {
                float4 q = s4[j];
                float tv = fmaf(q.x, fx, fmaf(q.y, fyv, fmaf(q.z, fz, q.w)));
                float d2 = tv + pp;
                unsigned u = __float_as_uint(d2);
                upd2(k1c, k2c, (u & KEY_MASK) | (unsigned)j);
            }

            // rescan chain cc2 (32 pts): lowest index whose t matches t2v bits
            unsigned idx2x = IDX_MASK;
            #pragma unroll 4
            for (int j = cc2; j < NTS; j += 4) {
                float4 q = s4[j];
                float tv = fmaf(q.x, fx, fmaf(q.y, fyv, fmaf(q.z, fz, q.w)));
                if (__float_as_int(tv) == t2b) idx2x = min(idx2x, (unsigned)j);
            }
            float d2x = t2v + pp;
            unsigned kx = (__float_as_uint(d2x) & KEY_MASK) | idx2x;
            unsigned k2 = min(k2c, kx);

            const int m = mbase + qi * 128;
            g_pk[(b * MM + m) * NSPLIT + split] = make_uint2(k1c, k2);
        }
        __syncthreads();
        if (tid == 0) {
            __threadfence();
            doFin = (atomicInc(&g_gc[grp], 31u) == 31u);
        }
        __syncthreads();

        if (doFin) {
            // ---- merge the 32 splits for this (b, mchunk): 512 m's ----
            float vsum = 0.0f;
            const uint4* pk4 = (const uint4*)g_pk;   // 16 uint4 per m
            #pragma unroll
            for (int qi = 0; qi < 4; qi++) {
                const int t = b * MM + mchunk * 512 + tid + qi * 128;
                float d1 = 1e30f, d2v = 1e30f;
                int n1 = 0, n2 = 0;
                #pragma unroll
                for (int q = 0; q < 16; q++) {
                    uint4 kk = pk4[t * 16 + q];
                    unsigned keys[4] = { kk.x, kk.y, kk.z, kk.w };
                    #pragma unroll
                    for (int i = 0; i < 4; i++) {
                        const int sp = q * 2 + (i >> 1);
                        unsigned key = keys[i];
                        float df = __uint_as_float(key & KEY_MASK);
                        int   nn = (int)(key & IDX_MASK) + sp * NTS;
                        if (df < d1)       { d2v = d1; n2 = n1; d1 = df; n1 = nn; }
                        else if (df < d2v) { d2v = df; n2 = nn; }
                    }
                }

                float cd = sqrtf(fmaxf(d1, 1e-12f));

                const float* nr = nori + (size_t)t * 3;
                const float* f1 = shape + ((size_t)(b * NN + n1)) * 6 + 3;
                const float* f2 = shape + ((size_t)(b * NN + n2)) * 6 + 3;
                float dot1 = nr[0] * f1[0] + nr[1] * f1[1] + nr[2] * f1[2];
                float dot2 = nr[0] * f2[0] + nr[1] * f2[1] + nr[2] * f2[2];

                vsum += 1e-4f * cd + (0.001f / (float)BB) * 0.5f * (fabsf(dot1) + fabsf(dot2));
            }
            float bsum = blockSum128(vsum);

            if (tid == 0) {
                g_pm[grp] = bsum;
                __threadfence();
                lastUnit = (atomicInc(&g_cnt, 159u) == 159u);
            }
            __syncthreads();
            if (lastUnit) finalize(out);
        }
    } else {
        // ================= shape part (cd1, 4 n-queries, quarter-M tiles) ====
        const int sb      = bid - 1024;
        const int b       = sb >> 5;        // 16
        const int r2      = sb & 31;
        const int nchunk  = r2 >> 2;        // 8
        const int quarter = r2 & 3;         // 4
        const int mbase   = quarter * MTS;
        const int grp     = b * 8 + nchunk;

        for (int i = tid; i < MTS; i += 128) {
            const float* s = skel + ((size_t)(b * MM + mbase + i)) * 3;
            float X = s[0], Y = s[1], Z = s[2];
            sx[i] = X; sy[i] = Y; sz[i] = Z;
            sw[i] = X * X + Y * Y + Z * Z;
        }
        __syncthreads();

        u64 m2x[4], m2y[4], m2z[4];
        #pragma unroll
        for (int qi = 0; qi < 4; qi++) {
            const int n = nchunk * 512 + tid + qi * 128;
            const float* p = shape + ((size_t)(b * NN + n)) * 6;
            float px = p[0], py = p[1], pz = p[2];
            m2x[qi] = pk2(-2.0f * px, -2.0f * px);
            m2y[qi] = pk2(-2.0f * py, -2.0f * py);
            m2z[qi] = pk2(-2.0f * pz, -2.0f * pz);
        }

        float mn[4][4];
        #pragma unroll
        for (int qi = 0; qi < 4; qi++)
            #pragma unroll
            for (int i = 0; i < 4; i++) mn[qi][i] = 1e30f;

        const ulonglong2* x2 = (const ulonglong2*)sx;
        const ulonglong2* y2 = (const ulonglong2*)sy;
        const ulonglong2* z2 = (const ulonglong2*)sz;
        const ulonglong2* w2 = (const ulonglong2*)sw;

        #pragma unroll 2
        for (int j = 0; j < MTS; j += 4) {
            const int g = j >> 2;
            ulonglong2 xa = x2[g], ya = y2[g], za = z2[g], wa = w2[g];

            #pragma unroll
            for (int qi = 0; qi < 4; qi++) {
                u64 t01 = fmx2(xa.x, m2x[qi], fmx2(ya.x, m2y[qi], fmx2(za.x, m2z[qi], wa.x)));
                u64 t23 = fmx2(xa.y, m2x[qi], fmx2(ya.y, m2y[qi], fmx2(za.y, m2z[qi], wa.y)));
                float f0, f1, f2, f3;
                upkf(t01, f0, f1);
                upkf(t23, f2, f3);
                mn[qi][0] = fminf(mn[qi][0], f0);
                mn[qi][1] = fminf(mn[qi][1], f1);
                mn[qi][2] = fminf(mn[qi][2], f2);
                mn[qi][3] = fminf(mn[qi][3], f3);
            }
        }

        #pragma unroll
        for (int qi = 0; qi < 4; qi++) {
            float tmin = fminf(fminf(mn[qi][0], mn[qi][1]), fminf(mn[qi][2], mn[qi][3]));
            g_sm[(grp * MSPLIT + quarter) * 512 + tid + qi * 128] = tmin;
        }
        __syncthreads();
        if (tid == 0) {
            __threadfence();
            doFin = (atomicInc(&g_sc[grp], 3u) == 3u);
        }
        __syncthreads();

        if (doFin) {
            float vsum = 0.0f;
            #pragma unroll
            for (int qi = 0; qi < 4; qi++) {
                const int idx = tid + qi * 128;
                float t0 = g_sm[(grp * MSPLIT + 0) * 512 + idx];
                float t1 = g_sm[(grp * MSPLIT + 1) * 512 + idx];
                float t2 = g_sm[(grp * MSPLIT + 2) * 512 + idx];
                float t3 = g_sm[(grp * MSPLIT + 3) * 512 + idx];
                float tm = fminf(fminf(t0, t1), fminf(t2, t3));
                const int n = nchunk * 512 + idx;
                const float* pq = shape + ((size_t)(b * NN + n)) * 6;
                float ppx = pq[0], ppy = pq[1], ppz = pq[2];
                float ppv = ppx * ppx + ppy * ppy + ppz * ppz;
                float dmin = ppv + tm;
                vsum += 1e-4f * sqrtf(fmaxf(dmin, 1e-12f));
            }

            float bsum = blockSum128(vsum);
            if (tid == 0) {
                g_ps[grp] = bsum;
                __threadfence();
                lastUnit = (atomicInc(&g_cnt, 159u) == 159u);
            }
            __syncthreads();
            if (lastUnit) finalize(out);
        }
    }
}

extern "C" void kernel_launch(void* const* d_in, const int* in_sizes, int n_in,
                              void* d_out, int out_size) {
    const float* shape = (const float*)d_in[0];  // (B, N, 6)
    const float* skel  = (const float*)d_in[1];  // (B, M, 3)
    const float* nori  = (const float*)d_in[2];  // (B, M, 3)
    float* out = (float*)d_out;

    k_all<<<1536, 128>>>(shape, skel, nori, out);
}

// round 14
// speedup vs baseline: 1.3755x; 1.3755x over previous
#include <cuda_runtime.h>
#include <math.h>

#define BB 16
#define NN 4096
#define MM 1024
#define NSPLIT 16
#define NTS (NN / NSPLIT)   // 256: skel tile size
#define MSPLIT 4
#define MTS (MM / MSPLIT)   // 256: shape tile size

#define KEY_MASK 0xFFFFFC00u
#define IDX_MASK 0x000003FFu

typedef unsigned long long u64;

// scratch (static device globals: no allocation allowed)
__device__ uint2        g_pk[BB * MM * NSPLIT];      // per-split (best, second) keys
__device__ float        g_sm[128 * MSPLIT * 512];    // shape quarter-tile partial tmins
__device__ float        g_ps[128];                   // shape-group partials (16*8)
__device__ float        g_pm[32];                    // merge-group partials (16*2)
__device__ unsigned int g_gc[32];                    // skel merge counters (wrap 15)
__device__ unsigned int g_sc[128];                   // shape combine counters (wrap 3)
__device__ unsigned int g_cnt = 0;                   // global counter (160 units)

// ---- packed f32x2 helpers ----
__device__ __forceinline__ u64 fmx2(u64 a, u64 b, u64 c) {
    u64 r; asm("fma.rn.f32x2 %0,%1,%2,%3;" : "=l"(r) : "l"(a), "l"(b), "l"(c)); return r;
}
__device__ __forceinline__ u64 pk2(float a, float b) {
    u64 r; asm("mov.b64 %0,{%1,%2};" : "=l"(r) : "f"(a), "f"(b)); return r;
}
__device__ __forceinline__ void upkf(u64 v, float& a, float& b) {
    asm("mov.b64 {%0,%1},%2;" : "=f"(a), "=f"(b) : "l"(v));
}

// branch-free top-2 update on packed keys (positive-float uint ordering)
__device__ __forceinline__ void upd2(unsigned& b1, unsigned& b2, unsigned k) {
    unsigned mx = max(k, b1);
    b2 = min(b2, mx);
    b1 = min(b1, k);
}
// float variant (correct IEEE order incl. negatives; no NaNs here)
__device__ __forceinline__ void upd2f(float& b1, float& b2, float k) {
    float mx = fmaxf(k, b1);
    b2 = fminf(b2, mx);
    b1 = fminf(b1, k);
}

__device__ __forceinline__ float blockSum128(float v) {
    #pragma unroll
    for (int o = 16; o; o >>= 1) v += __shfl_xor_sync(0xFFFFFFFFu, v, o);
    __shared__ float ws[4];
    int w = threadIdx.x >> 5, l = threadIdx.x & 31;
    if (l == 0) ws[w] = v;
    __syncthreads();
    if (threadIdx.x == 0) v = ws[0] + ws[1] + ws[2] + ws[3];
    return v;  // valid on thread 0
}

// final scalar reduction over all 160 partials (block-uniform call, 128 thr)
__device__ __forceinline__ void finalize(float* out) {
    double acc = (double)g_ps[threadIdx.x];
    if (threadIdx.x < 32) acc += (double)g_pm[threadIdx.x];
    #pragma unroll
    for (int o = 16; o; o >>= 1) acc += __shfl_xor_sync(0xFFFFFFFFu, acc, o);
    __shared__ double wd[4];
    if ((threadIdx.x & 31) == 0) wd[threadIdx.x >> 5] = acc;
    __syncthreads();
    if (threadIdx.x == 0) out[0] = (float)(wd[0] + wd[1] + wd[2] + wd[3]);
}

// ---------------------------------------------------------------------------
// Single fused kernel, 4 queries/thread, 256-pt tiles (R11 geometry).
//   blocks [0, 512):   skel: 512 m's vs one 256-pt N-split (16 splits).
//                      Last split-block per (b,mchunk) merges + cd2/normals.
//   blocks [512,1024): shape: 512 n's vs one 256-pt M-quarter (4 quarters).
//                      Last quarter-block per (b,nchunk) combines -> cd1.
// grid = 1024, block = 128
// ---------------------------------------------------------------------------
__global__ void __launch_bounds__(128) k_all(const float* __restrict__ shape,
                                             const float* __restrict__ skel,
                                             const float* __restrict__ nori,
                                             float* __restrict__ out) {
    __shared__ __align__(16) float sx[256];
    __shared__ __align__(16) float sy[256];
    __shared__ __align__(16) float sz[256];
    __shared__ __align__(16) float sw[256];
    __shared__ __align__(16) float4 s4[256];   // AoS shadow for rescans
    __shared__ bool doFin, lastUnit;

    const int bid = blockIdx.x;
    const int tid = threadIdx.x;

    if (bid < 512) {
        // ================= skel part (4 m-queries per thread) ================
        const int b      = bid >> 5;        // 16
        const int r      = bid & 31;
        const int split  = r & 15;          // 16
        const int mchunk = r >> 4;          // 2
        const int nbase  = split * NTS;
        const int grp    = b * 2 + mchunk;

        for (int i = tid; i < NTS; i += 128) {
            const float* p = shape + ((size_t)(b * NN + nbase + i)) * 6;
            float X = p[0], Y = p[1], Z = p[2];
            float W = X * X + Y * Y + Z * Z;
            sx[i] = X; sy[i] = Y; sz[i] = Z; sw[i] = W;
            s4[i] = make_float4(X, Y, Z, W);
        }
        __syncthreads();

        const int mbase = mchunk * 512 + tid;
        float ppq[4];
        u64 m2x[4], m2y[4], m2z[4];
        float c[4][8];
        #pragma unroll
        for (int qi = 0; qi < 4; qi++) {
            const int m = mbase + qi * 128;
            const float* s = skel + ((size_t)(b * MM + m)) * 3;
            float qx = s[0], qy = s[1], qz = s[2];
            ppq[qi] = qx * qx + qy * qy + qz * qz;
            m2x[qi] = pk2(-2.0f * qx, -2.0f * qx);
            m2y[qi] = pk2(-2.0f * qy, -2.0f * qy);
            m2z[qi] = pk2(-2.0f * qz, -2.0f * qz);
            #pragma unroll
            for (int i = 0; i < 8; i++) c[qi][i] = 1e30f;
        }

        const ulonglong2* x2 = (const ulonglong2*)sx;
        const ulonglong2* y2 = (const ulonglong2*)sy;
        const ulonglong2* z2 = (const ulonglong2*)sz;
        const ulonglong2* w2 = (const ulonglong2*)sw;

        // chains = FLOAT minima of t = w - 2 p.s per mod-8 class; banked
        // sub-bodies keep only 4 u64 loads live at a time. Class of point j
        // is (j mod 4) + 4*((j>>2)&1) = j mod 8, identical to R11.
        for (int j = 0; j < NTS; j += 8) {
            const int g = j >> 2;
            {   // bank 0: points j .. j+3 -> chains 0..3
                ulonglong2 xa = x2[g], ya = y2[g], za = z2[g], wa = w2[g];
                #pragma unroll
                for (int qi = 0; qi < 4; qi++) {
                    u64 q01 = fmx2(xa.x, m2x[qi], fmx2(ya.x, m2y[qi], fmx2(za.x, m2z[qi], wa.x)));
                    u64 q23 = fmx2(xa.y, m2x[qi], fmx2(ya.y, m2y[qi], fmx2(za.y, m2z[qi], wa.y)));
                    float f0, f1, f2, f3;
                    upkf(q01, f0, f1);
                    upkf(q23, f2, f3);
                    c[qi][0] = fminf(c[qi][0], f0);
                    c[qi][1] = fminf(c[qi][1], f1);
                    c[qi][2] = fminf(c[qi][2], f2);
                    c[qi][3] = fminf(c[qi][3], f3);
                }
            }
            {   // bank 1: points j+4 .. j+7 -> chains 4..7
                ulonglong2 xb = x2[g + 1], yb = y2[g + 1], zb = z2[g + 1], wb = w2[g + 1];
                #pragma unroll
                for (int qi = 0; qi < 4; qi++) {
                    u64 q01 = fmx2(xb.x, m2x[qi], fmx2(yb.x, m2y[qi], fmx2(zb.x, m2z[qi], wb.x)));
                    u64 q23 = fmx2(xb.y, m2x[qi], fmx2(yb.y, m2y[qi], fmx2(zb.y, m2z[qi], wb.y)));
                    float f0, f1, f2, f3;
                    upkf(q01, f0, f1);
                    upkf(q23, f2, f3);
                    c[qi][4] = fminf(c[qi][4], f0);
                    c[qi][5] = fminf(c[qi][5], f1);
                    c[qi][6] = fminf(c[qi][6], f2);
                    c[qi][7] = fminf(c[qi][7], f3);
                }
            }
        }

        #pragma unroll
        for (int qi = 0; qi < 4; qi++) {
            // top-2 float values over the 8 chain minima
            float t1v = 1e30f, t2v = 1e30f;
            #pragma unroll
            for (int i = 0; i < 8; i++) upd2f(t1v, t2v, c[qi][i]);
            const int t1b = __float_as_int(t1v);
            const int t2b = __float_as_int(t2v);

            // cc1 = lowest chain attaining t1; cc2 = lowest other chain at t2
            int cc1 = 7;
            #pragma unroll
            for (int k = 6; k >= 0; k--) if (__float_as_int(c[qi][k]) == t1b) cc1 = k;
            int cc2 = (cc1 == 0) ? 1 : 0;
            #pragma unroll
            for (int k = 7; k >= 0; k--) if (__float_as_int(c[qi][k]) == t2b && k != cc1) cc2 = k;

            const float pp = ppq[qi];
            float fx, fy, fz, dum;
            upkf(m2x[qi], fx, dum);
            upkf(m2y[qi], fy, dum);
            upkf(m2z[qi], fz, dum);

            // rescan chain cc1 (32 pts): exact quantized top-2 with indices
            // (identical scalar FMA sequence -> bit-identical values)
            unsigned k1c = ~0u, k2c = ~0u;
            #pragma unroll 4
            for (int j = cc1; j < NTS; j += 8) {
                float4 q = s4[j];
                float tv = fmaf(q.x, fx, fmaf(q.y, fy, fmaf(q.z, fz, q.w)));
                float d2 = tv + pp;
                unsigned u = __float_as_uint(d2);
                upd2(k1c, k2c, (u & KEY_MASK) | (unsigned)j);
            }

            // rescan chain cc2 (32 pts): lowest index whose t matches t2v bits
            unsigned idx2x = IDX_MASK;
            #pragma unroll 4
            for (int j = cc2; j < NTS; j += 8) {
                float4 q = s4[j];
                float tv = fmaf(q.x, fx, fmaf(q.y, fy, fmaf(q.z, fz, q.w)));
                if (__float_as_int(tv) == t2b) idx2x = min(idx2x, (unsigned)j);
            }
            float d2x = t2v + pp;
            unsigned kx = (__float_as_uint(d2x) & KEY_MASK) | idx2x;
            unsigned k2 = min(k2c, kx);

            const int m = mbase + qi * 128;
            g_pk[(b * MM + m) * NSPLIT + split] = make_uint2(k1c, k2);
        }
        __syncthreads();
        if (tid == 0) {
            __threadfence();
            doFin = (atomicInc(&g_gc[grp], 15u) == 15u);
        }
        __syncthreads();

        if (doFin) {
            // ---- merge the 16 splits for this (b, mchunk): 512 m's ----
            float vsum = 0.0f;
            const uint4* pk4 = (const uint4*)g_pk;   // 8 uint4 per m
            #pragma unroll
            for (int qi = 0; qi < 4; qi++) {
                const int t = b * MM + mchunk * 512 + tid + qi * 128;
                float d1 = 1e30f, d2v = 1e30f;
                int n1 = 0, n2 = 0;
                #pragma unroll
                for (int q = 0; q < 8; q++) {
                    uint4 kk = pk4[t * 8 + q];
                    unsigned keys[4] = { kk.x, kk.y, kk.z, kk.w };
                    #pragma unroll
                    for (int i = 0; i < 4; i++) {
                        const int sp = q * 2 + (i >> 1);
                        unsigned key = keys[i];
                        float df = __uint_as_float(key & KEY_MASK);
                        int   nn = (int)(key & IDX_MASK) + sp * NTS;
                        if (df < d1)       { d2v = d1; n2 = n1; d1 = df; n1 = nn; }
                        else if (df < d2v) { d2v = df; n2 = nn; }
                    }
                }

                float cd = sqrtf(fmaxf(d1, 1e-12f));

                const float* nr = nori + (size_t)t * 3;
                const float* f1 = shape + ((size_t)(b * NN + n1)) * 6 + 3;
                const float* f2 = shape + ((size_t)(b * NN + n2)) * 6 + 3;
                float dot1 = nr[0] * f1[0] + nr[1] * f1[1] + nr[2] * f1[2];
                float dot2 = nr[0] * f2[0] + nr[1] * f2[1] + nr[2] * f2[2];

                vsum += 1e-4f * cd + (0.001f / (float)BB) * 0.5f * (fabsf(dot1) + fabsf(dot2));
            }
            float bsum = blockSum128(vsum);

            if (tid == 0) {
                g_pm[grp] = bsum;
                __threadfence();
                lastUnit = (atomicInc(&g_cnt, 159u) == 159u);
            }
            __syncthreads();
            if (lastUnit) finalize(out);
        }
    } else {
        // ================= shape part (cd1, 4 n-queries, quarter-M tiles) ====
        const int sb      = bid - 512;
        const int b       = sb >> 5;        // 16
        const int r2      = sb & 31;
        const int nchunk  = r2 >> 2;        // 8
        const int quarter = r2 & 3;         // 4
        const int mbase   = quarter * MTS;
        const int grp     = b * 8 + nchunk;

        for (int i = tid; i < MTS; i += 128) {
            const float* s = skel + ((size_t)(b * MM + mbase + i)) * 3;
            float X = s[0], Y = s[1], Z = s[2];
            sx[i] = X; sy[i] = Y; sz[i] = Z;
            sw[i] = X * X + Y * Y + Z * Z;
        }
        __syncthreads();

        u64 m2x[4], m2y[4], m2z[4];
        #pragma unroll
        for (int qi = 0; qi < 4; qi++) {
            const int n = nchunk * 512 + tid + qi * 128;
            const float* p = shape + ((size_t)(b * NN + n)) * 6;
            float px = p[0], py = p[1], pz = p[2];
            m2x[qi] = pk2(-2.0f * px, -2.0f * px);
            m2y[qi] = pk2(-2.0f * py, -2.0f * py);
            m2z[qi] = pk2(-2.0f * pz, -2.0f * pz);
        }

        float mn[4][4];
        #pragma unroll
        for (int qi = 0; qi < 4; qi++)
            #pragma unroll
            for (int i = 0; i < 4; i++) mn[qi][i] = 1e30f;

        const ulonglong2* x2 = (const ulonglong2*)sx;
        const ulonglong2* y2 = (const ulonglong2*)sy;
        const ulonglong2* z2 = (const ulonglong2*)sz;
        const ulonglong2* w2 = (const ulonglong2*)sw;

        #pragma unroll 2
        for (int j = 0; j < MTS; j += 4) {
            const int g = j >> 2;
            ulonglong2 xa = x2[g], ya = y2[g], za = z2[g], wa = w2[g];

            #pragma unroll
            for (int qi = 0; qi < 4; qi++) {
                u64 t01 = fmx2(xa.x, m2x[qi], fmx2(ya.x, m2y[qi], fmx2(za.x, m2z[qi], wa.x)));
                u64 t23 = fmx2(xa.y, m2x[qi], fmx2(ya.y, m2y[qi], fmx2(za.y, m2z[qi], wa.y)));
                float f0, f1, f2, f3;
                upkf(t01, f0, f1);
                upkf(t23, f2, f3);
                mn[qi][0] = fminf(mn[qi][0], f0);
                mn[qi][1] = fminf(mn[qi][1], f1);
                mn[qi][2] = fminf(mn[qi][2], f2);
                mn[qi][3] = fminf(mn[qi][3], f3);
            }
        }

        #pragma unroll
        for (int qi = 0; qi < 4; qi++) {
            float tmin = fminf(fminf(mn[qi][0], mn[qi][1]), fminf(mn[qi][2], mn[qi][3]));
            g_sm[(grp * MSPLIT + quarter) * 512 + tid + qi * 128] = tmin;
        }
        __syncthreads();
        if (tid == 0) {
            __threadfence();
            doFin = (atomicInc(&g_sc[grp], 3u) == 3u);
        }
        __syncthreads();

        if (doFin) {
            float vsum = 0.0f;
            #pragma unroll
            for (int qi = 0; qi < 4; qi++) {
                const int idx = tid + qi * 128;
                float t0 = g_sm[(grp * MSPLIT + 0) * 512 + idx];
                float t1 = g_sm[(grp * MSPLIT + 1) * 512 + idx];
                float t2 = g_sm[(grp * MSPLIT + 2) * 512 + idx];
                float t3 = g_sm[(grp * MSPLIT + 3) * 512 + idx];
                float tm = fminf(fminf(t0, t1), fminf(t2, t3));
                const int n = nchunk * 512 + idx;
                const float* pq = shape + ((size_t)(b * NN + n)) * 6;
                float ppx = pq[0], ppy = pq[1], ppz = pq[2];
                float ppv = ppx * ppx + ppy * ppy + ppz * ppz;
                float dmin = ppv + tm;
                vsum += 1e-4f * sqrtf(fmaxf(dmin, 1e-12f));
            }

            float bsum = blockSum128(vsum);
            if (tid == 0) {
                g_ps[grp] = bsum;
                __threadfence();
                lastUnit = (atomicInc(&g_cnt, 159u) == 159u);
            }
            __syncthreads();
            if (lastUnit) finalize(out);
        }
    }
}

extern "C" void kernel_launch(void* const* d_in, const int* in_sizes, int n_in,
                              void* d_out, int out_size) {
    const float* shape = (const float*)d_in[0];  // (B, N, 6)
    const float* skel  = (const float*)d_in[1];  // (B, M, 3)
    const float* nori  = (const float*)d_in[2];  // (B, M, 3)
    float* out = (float*)d_out;

    k_all<<<1024, 128>>>(shape, skel, nori, out);
}

// round 15
// speedup vs baseline: 1.4456x; 1.0510x over previous
#include <cuda_runtime.h>
#include <math.h>

#define BB 16
#define NN 4096
#define MM 1024
#define NSPLIT 16
#define NTS (NN / NSPLIT)   // 256: skel tile size
#define MSPLIT 4
#define MTS (MM / MSPLIT)   // 256: shape tile size

#define KEY_MASK 0xFFFFFC00u
#define IDX_MASK 0x000003FFu

typedef unsigned long long u64;

// scratch (static device globals: no allocation allowed)
__device__ uint2        g_pk[BB * MM * NSPLIT];      // per-split (best, second) keys
__device__ float        g_sm[256 * MSPLIT * 256];    // shape quarter-tile partial tmins
__device__ float        g_ps[256];                   // shape-group partials (16*16)
__device__ float        g_pm[64];                    // merge-group partials (16*4)
__device__ unsigned int g_gc[64];                    // skel merge counters (wrap 15)
__device__ unsigned int g_sc[256];                   // shape combine counters (wrap 3)
__device__ unsigned int g_cnt = 0;                   // global counter (320 units)

// ---- packed f32x2 helpers ----
__device__ __forceinline__ u64 fmx2(u64 a, u64 b, u64 c) {
    u64 r; asm("fma.rn.f32x2 %0,%1,%2,%3;" : "=l"(r) : "l"(a), "l"(b), "l"(c)); return r;
}
__device__ __forceinline__ u64 pk2(float a, float b) {
    u64 r; asm("mov.b64 %0,{%1,%2};" : "=l"(r) : "f"(a), "f"(b)); return r;
}
__device__ __forceinline__ void upkf(u64 v, float& a, float& b) {
    asm("mov.b64 {%0,%1},%2;" : "=f"(a), "=f"(b) : "l"(v));
}

// branch-free top-2 update on packed keys (positive-float uint ordering)
__device__ __forceinline__ void upd2(unsigned& b1, unsigned& b2, unsigned k) {
    unsigned mx = max(k, b1);
    b2 = min(b2, mx);
    b1 = min(b1, k);
}
// float variant (correct IEEE order incl. negatives; no NaNs here)
__device__ __forceinline__ void upd2f(float& b1, float& b2, float k) {
    float mx = fmaxf(k, b1);
    b2 = fminf(b2, mx);
    b1 = fminf(b1, k);
}

__device__ __forceinline__ float blockSum128(float v) {
    #pragma unroll
    for (int o = 16; o; o >>= 1) v += __shfl_xor_sync(0xFFFFFFFFu, v, o);
    __shared__ float ws[4];
    int w = threadIdx.x >> 5, l = threadIdx.x & 31;
    if (l == 0) ws[w] = v;
    __syncthreads();
    if (threadIdx.x == 0) v = ws[0] + ws[1] + ws[2] + ws[3];
    return v;  // valid on thread 0
}

// final scalar reduction over all 320 partials (block-uniform call, 128 thr)
__device__ __forceinline__ void finalize(float* out) {
    double acc = (double)g_ps[threadIdx.x] + (double)g_ps[threadIdx.x + 128];
    if (threadIdx.x < 64) acc += (double)g_pm[threadIdx.x];
    #pragma unroll
    for (int o = 16; o; o >>= 1) acc += __shfl_xor_sync(0xFFFFFFFFu, acc, o);
    __shared__ double wd[4];
    if ((threadIdx.x & 31) == 0) wd[threadIdx.x >> 5] = acc;
    __syncthreads();
    if (threadIdx.x == 0) out[0] = (float)(wd[0] + wd[1] + wd[2] + wd[3]);
}

// ---------------------------------------------------------------------------
// Single fused kernel, 2 queries/thread, 256-pt tiles (R11 structure).
//   blocks [0, 1024):    skel: 256 m's vs one 256-pt N-split (16 splits).
//                        Last split-block per (b,mchunk) merges + cd2/normals.
//   blocks [1024, 2048): shape: 256 n's vs one 256-pt M-quarter (4 quarters).
//                        Last quarter-block per (b,nchunk) combines -> cd1.
// grid = 2048, block = 128; min 9 blocks/SM (<=56 regs) for occupancy.
// ---------------------------------------------------------------------------
__global__ void __launch_bounds__(128, 9) k_all(const float* __restrict__ shape,
                                                const float* __restrict__ skel,
                                                const float* __restrict__ nori,
                                                float* __restrict__ out) {
    __shared__ __align__(16) float sx[256];
    __shared__ __align__(16) float sy[256];
    __shared__ __align__(16) float sz[256];
    __shared__ __align__(16) float sw[256];
    __shared__ __align__(16) float4 s4[256];   // AoS shadow for rescans
    __shared__ bool doFin, lastUnit;

    const int bid = blockIdx.x;
    const int tid = threadIdx.x;

    if (bid < 1024) {
        // ================= skel part (2 m-queries per thread) ================
        const int b      = bid >> 6;        // 16
        const int r      = bid & 63;
        const int split  = r & 15;          // 16
        const int mchunk = r >> 4;          // 4
        const int nbase  = split * NTS;
        const int grp    = b * 4 + mchunk;

        for (int i = tid; i < NTS; i += 128) {
            const float* p = shape + ((size_t)(b * NN + nbase + i)) * 6;
            float X = p[0], Y = p[1], Z = p[2];
            float W = X * X + Y * Y + Z * Z;
            sx[i] = X; sy[i] = Y; sz[i] = Z; sw[i] = W;
            s4[i] = make_float4(X, Y, Z, W);
        }
        __syncthreads();

        const int mbase = mchunk * 256 + tid;
        float ppq[2];
        u64 m2x[2], m2y[2], m2z[2];
        float c[2][8];
        #pragma unroll
        for (int qi = 0; qi < 2; qi++) {
            const int m = mbase + qi * 128;
            const float* s = skel + ((size_t)(b * MM + m)) * 3;
            float qx = s[0], qy = s[1], qz = s[2];
            ppq[qi] = qx * qx + qy * qy + qz * qz;
            m2x[qi] = pk2(-2.0f * qx, -2.0f * qx);
            m2y[qi] = pk2(-2.0f * qy, -2.0f * qy);
            m2z[qi] = pk2(-2.0f * qz, -2.0f * qz);
            #pragma unroll
            for (int i = 0; i < 8; i++) c[qi][i] = 1e30f;
        }

        const ulonglong2* x2 = (const ulonglong2*)sx;
        const ulonglong2* y2 = (const ulonglong2*)sy;
        const ulonglong2* z2 = (const ulonglong2*)sz;
        const ulonglong2* w2 = (const ulonglong2*)sw;

        // chains track FLOAT minima of t = w - 2 p.s per mod-8 class;
        // pp is a per-query constant, folded in after the loop.
        for (int j = 0; j < NTS; j += 8) {
            const int g = j >> 2;
            ulonglong2 xa = x2[g], xb = x2[g + 1];
            ulonglong2 ya = y2[g], yb = y2[g + 1];
            ulonglong2 za = z2[g], zb = z2[g + 1];
            ulonglong2 wa = w2[g], wb = w2[g + 1];

            #pragma unroll
            for (int qi = 0; qi < 2; qi++) {
                u64 q0 = fmx2(xa.x, m2x[qi], fmx2(ya.x, m2y[qi], fmx2(za.x, m2z[qi], wa.x)));
                u64 q1 = fmx2(xa.y, m2x[qi], fmx2(ya.y, m2y[qi], fmx2(za.y, m2z[qi], wa.y)));
                u64 q2 = fmx2(xb.x, m2x[qi], fmx2(yb.x, m2y[qi], fmx2(zb.x, m2z[qi], wb.x)));
                u64 q3 = fmx2(xb.y, m2x[qi], fmx2(yb.y, m2y[qi], fmx2(zb.y, m2z[qi], wb.y)));

                float f0, f1, f2, f3, f4, f5, f6, f7;
                upkf(q0, f0, f1);
                upkf(q1, f2, f3);
                upkf(q2, f4, f5);
                upkf(q3, f6, f7);
                c[qi][0] = fminf(c[qi][0], f0);
                c[qi][1] = fminf(c[qi][1], f1);
                c[qi][2] = fminf(c[qi][2], f2);
                c[qi][3] = fminf(c[qi][3], f3);
                c[qi][4] = fminf(c[qi][4], f4);
                c[qi][5] = fminf(c[qi][5], f5);
                c[qi][6] = fminf(c[qi][6], f6);
                c[qi][7] = fminf(c[qi][7], f7);
            }
        }

        #pragma unroll
        for (int qi = 0; qi < 2; qi++) {
            // top-2 float values over the 8 chain minima
            float t1v = 1e30f, t2v = 1e30f;
            #pragma unroll
            for (int i = 0; i < 8; i++) upd2f(t1v, t2v, c[qi][i]);
            const int t1b = __float_as_int(t1v);
            const int t2b = __float_as_int(t2v);

            // cc1 = lowest chain attaining t1; cc2 = lowest other chain at t2
            int cc1 = 7;
            #pragma unroll
            for (int k = 6; k >= 0; k--) if (__float_as_int(c[qi][k]) == t1b) cc1 = k;
            int cc2 = (cc1 == 0) ? 1 : 0;
            #pragma unroll
            for (int k = 7; k >= 0; k--) if (__float_as_int(c[qi][k]) == t2b && k != cc1) cc2 = k;

            const float pp = ppq[qi];
            float fx, fy, fz, dum;
            upkf(m2x[qi], fx, dum);
            upkf(m2y[qi], fy, dum);
            upkf(m2z[qi], fz, dum);

            // fused dual rescan (32 iters): chain cc1 exact quantized top-2
            // with indices; chain cc2 lowest index matching its min value.
            // (identical scalar FMA sequence -> bit-identical values)
            unsigned k1c = ~0u, k2c = ~0u;
            unsigned idx2x = IDX_MASK;
            #pragma unroll 4
            for (int j = 0; j < NTS; j += 8) {
                float4 qa = s4[j + cc1];
                float4 qb = s4[j + cc2];
                float ta = fmaf(qa.x, fx, fmaf(qa.y, fy, fmaf(qa.z, fz, qa.w)));
                float tb = fmaf(qb.x, fx, fmaf(qb.y, fy, fmaf(qb.z, fz, qb.w)));
                float d2 = ta + pp;
                unsigned u = __float_as_uint(d2);
                upd2(k1c, k2c, (u & KEY_MASK) | (unsigned)(j + cc1));
                if (__float_as_int(tb) == t2b) idx2x = min(idx2x, (unsigned)(j + cc2));
            }
            float d2x = t2v + pp;
            unsigned kx = (__float_as_uint(d2x) & KEY_MASK) | idx2x;
            unsigned k2 = min(k2c, kx);

            const int m = mbase + qi * 128;
            g_pk[(b * MM + m) * NSPLIT + split] = make_uint2(k1c, k2);
        }
        __syncthreads();
        if (tid == 0) {
            __threadfence();
            doFin = (atomicInc(&g_gc[grp], 15u) == 15u);
        }
        __syncthreads();

        if (doFin) {
            // ---- merge the 16 splits for this (b, mchunk): 256 m's ----
            float vsum = 0.0f;
            const uint4* pk4 = (const uint4*)g_pk;   // 8 uint4 per m
            #pragma unroll
            for (int qi = 0; qi < 2; qi++) {
                const int t = b * MM + mchunk * 256 + tid + qi * 128;
                float d1 = 1e30f, d2v = 1e30f;
                int n1 = 0, n2 = 0;
                #pragma unroll
                for (int q = 0; q < 8; q++) {
                    uint4 kk = pk4[t * 8 + q];
                    unsigned keys[4] = { kk.x, kk.y, kk.z, kk.w };
                    #pragma unroll
                    for (int i = 0; i < 4; i++) {
                        const int sp = q * 2 + (i >> 1);
                        unsigned key = keys[i];
                        float df = __uint_as_float(key & KEY_MASK);
                        int   nn = (int)(key & IDX_MASK) + sp * NTS;
                        if (df < d1)       { d2v = d1; n2 = n1; d1 = df; n1 = nn; }
                        else if (df < d2v) { d2v = df; n2 = nn; }
                    }
                }

                float cd = sqrtf(fmaxf(d1, 1e-12f));

                const float* nr = nori + (size_t)t * 3;
                const float* f1 = shape + ((size_t)(b * NN + n1)) * 6 + 3;
                const float* f2 = shape + ((size_t)(b * NN + n2)) * 6 + 3;
                float dot1 = nr[0] * f1[0] + nr[1] * f1[1] + nr[2] * f1[2];
                float dot2 = nr[0] * f2[0] + nr[1] * f2[1] + nr[2] * f2[2];

                vsum += 1e-4f * cd + (0.001f / (float)BB) * 0.5f * (fabsf(dot1) + fabsf(dot2));
            }
            float bsum = blockSum128(vsum);

            if (tid == 0) {
                g_pm[grp] = bsum;
                __threadfence();
                lastUnit = (atomicInc(&g_cnt, 319u) == 319u);
            }
            __syncthreads();
            if (lastUnit) finalize(out);
        }
    } else {
        // ================= shape part (cd1, 2 n-queries, quarter-M tiles) ====
        const int sb      = bid - 1024;
        const int b       = sb >> 6;        // 16
        const int r2      = sb & 63;
        const int nchunk  = r2 >> 2;        // 16
        const int quarter = r2 & 3;         // 4
        const int mbase   = quarter * MTS;
        const int grp     = b * 16 + nchunk;

        for (int i = tid; i < MTS; i += 128) {
            const float* s = skel + ((size_t)(b * MM + mbase + i)) * 3;
            float X = s[0], Y = s[1], Z = s[2];
            sx[i] = X; sy[i] = Y; sz[i] = Z;
            sw[i] = X * X + Y * Y + Z * Z;
        }
        __syncthreads();

        u64 m2x[2], m2y[2], m2z[2];
        #pragma unroll
        for (int qi = 0; qi < 2; qi++) {
            const int n = nchunk * 256 + tid + qi * 128;
            const float* p = shape + ((size_t)(b * NN + n)) * 6;
            float px = p[0], py = p[1], pz = p[2];
            m2x[qi] = pk2(-2.0f * px, -2.0f * px);
            m2y[qi] = pk2(-2.0f * py, -2.0f * py);
            m2z[qi] = pk2(-2.0f * pz, -2.0f * pz);
        }

        float mn[2][8];
        #pragma unroll
        for (int qi = 0; qi < 2; qi++)
            #pragma unroll
            for (int i = 0; i < 8; i++) mn[qi][i] = 1e30f;

        const ulonglong2* x2 = (const ulonglong2*)sx;
        const ulonglong2* y2 = (const ulonglong2*)sy;
        const ulonglong2* z2 = (const ulonglong2*)sz;
        const ulonglong2* w2 = (const ulonglong2*)sw;

        for (int j = 0; j < MTS; j += 8) {
            const int g = j >> 2;
            ulonglong2 xa = x2[g], xb = x2[g + 1];
            ulonglong2 ya = y2[g], yb = y2[g + 1];
            ulonglong2 za = z2[g], zb = z2[g + 1];
            ulonglong2 wa = w2[g], wb = w2[g + 1];

            #pragma unroll
            for (int qi = 0; qi < 2; qi++) {
                u64 t0 = fmx2(xa.x, m2x[qi], fmx2(ya.x, m2y[qi], fmx2(za.x, m2z[qi], wa.x)));
                u64 t1 = fmx2(xa.y, m2x[qi], fmx2(ya.y, m2y[qi], fmx2(za.y, m2z[qi], wa.y)));
                u64 t2 = fmx2(xb.x, m2x[qi], fmx2(yb.x, m2y[qi], fmx2(zb.x, m2z[qi], wb.x)));
                u64 t3 = fmx2(xb.y, m2x[qi], fmx2(yb.y, m2y[qi], fmx2(zb.y, m2z[qi], wb.y)));

                float f0, f1, f2, f3, f4, f5, f6, f7;
                upkf(t0, f0, f1);
                upkf(t1, f2, f3);
                upkf(t2, f4, f5);
                upkf(t3, f6, f7);
                mn[qi][0] = fminf(mn[qi][0], f0);
                mn[qi][1] = fminf(mn[qi][1], f1);
                mn[qi][2] = fminf(mn[qi][2], f2);
                mn[qi][3] = fminf(mn[qi][3], f3);
                mn[qi][4] = fminf(mn[qi][4], f4);
                mn[qi][5] = fminf(mn[qi][5], f5);
                mn[qi][6] = fminf(mn[qi][6], f6);
                mn[qi][7] = fminf(mn[qi][7], f7);
            }
        }

        #pragma unroll
        for (int qi = 0; qi < 2; qi++) {
            float tmin = fminf(fminf(fminf(mn[qi][0], mn[qi][1]), fminf(mn[qi][2], mn[qi][3])),
                               fminf(fminf(mn[qi][4], mn[qi][5]), fminf(mn[qi][6], mn[qi][7])));
            g_sm[(grp * MSPLIT + quarter) * 256 + tid + qi * 128] = tmin;
        }
        __syncthreads();
        if (tid == 0) {
            __threadfence();
            doFin = (atomicInc(&g_sc[grp], 3u) == 3u);
        }
        __syncthreads();

        if (doFin) {
            float vsum = 0.0f;
            #pragma unroll
            for (int qi = 0; qi < 2; qi++) {
                const int idx = tid + qi * 128;
                float t0 = g_sm[(grp * MSPLIT + 0) * 256 + idx];
                float t1 = g_sm[(grp * MSPLIT + 1) * 256 + idx];
                float t2 = g_sm[(grp * MSPLIT + 2) * 256 + idx];
                float t3 = g_sm[(grp * MSPLIT + 3) * 256 + idx];
                float tm = fminf(fminf(t0, t1), fminf(t2, t3));
                const int n = nchunk * 256 + idx;
                const float* pq = shape + ((size_t)(b * NN + n)) * 6;
                float ppx = pq[0], ppy = pq[1], ppz = pq[2];
                float ppv = ppx * ppx + ppy * ppy + ppz * ppz;
                float dmin = ppv + tm;
                vsum += 1e-4f * sqrtf(fmaxf(dmin, 1e-12f));
            }

            float bsum = blockSum128(vsum);
            if (tid == 0) {
                g_ps[grp] = bsum;
                __threadfence();
                lastUnit = (atomicInc(&g_cnt, 319u) == 319u);
            }
            __syncthreads();
            if (lastUnit) finalize(out);
        }
    }
}

extern "C" void kernel_launch(void* const* d_in, const int* in_sizes, int n_in,
                              void* d_out, int out_size) {
    const float* shape = (const float*)d_in[0];  // (B, N, 6)
    const float* skel  = (const float*)d_in[1];  // (B, M, 3)
    const float* nori  = (const float*)d_in[2];  // (B, M, 3)
    float* out = (float*)d_out;

    k_all<<<2048, 128>>>(shape, skel, nori, out);
}

// round 16
// speedup vs baseline: 1.5109x; 1.0452x over previous
#include <cuda_runtime.h>
#include <math.h>

#define BB 16
#define NN 4096
#define MM 1024
#define NSPLIT 16
#define NTS (NN / NSPLIT)   // 256: skel tile size
#define MSPLIT 4
#define MTS (MM / MSPLIT)   // 256: shape tile size

#define KEY_MASK 0xFFFFFC00u
#define IDX_MASK 0x000003FFu

typedef unsigned long long u64;

// scratch (static device globals: no allocation allowed)
__device__ uint2        g_pk[BB * MM * NSPLIT];      // per-split (best, second) keys
__device__ float        g_sm[256 * MSPLIT * 256];    // shape quarter-tile partial tmins
__device__ float        g_ps[256];                   // shape-group partials (16*16)
__device__ float        g_pm[64];                    // merge-group partials (16*4)
__device__ unsigned int g_gc[64];                    // skel merge counters (wrap 15)
__device__ unsigned int g_sc[256];                   // shape combine counters (wrap 3)
__device__ unsigned int g_cnt = 0;                   // global counter (320 units)

// ---- packed f32x2 helpers ----
__device__ __forceinline__ u64 fmx2(u64 a, u64 b, u64 c) {
    u64 r; asm("fma.rn.f32x2 %0,%1,%2,%3;" : "=l"(r) : "l"(a), "l"(b), "l"(c)); return r;
}
__device__ __forceinline__ u64 pk2(float a, float b) {
    u64 r; asm("mov.b64 %0,{%1,%2};" : "=l"(r) : "f"(a), "f"(b)); return r;
}
__device__ __forceinline__ void upkf(u64 v, float& a, float& b) {
    asm("mov.b64 {%0,%1},%2;" : "=f"(a), "=f"(b) : "l"(v));
}

// branch-free top-2 update on packed keys (positive-float uint ordering)
__device__ __forceinline__ void upd2(unsigned& b1, unsigned& b2, unsigned k) {
    unsigned mx = max(k, b1);
    b2 = min(b2, mx);
    b1 = min(b1, k);
}
// float variant (correct IEEE order incl. negatives; no NaNs here)
__device__ __forceinline__ void upd2f(float& b1, float& b2, float k) {
    float mx = fmaxf(k, b1);
    b2 = fminf(b2, mx);
    b1 = fminf(b1, k);
}

__device__ __forceinline__ float blockSum128(float v) {
    #pragma unroll
    for (int o = 16; o; o >>= 1) v += __shfl_xor_sync(0xFFFFFFFFu, v, o);
    __shared__ float ws[4];
    int w = threadIdx.x >> 5, l = threadIdx.x & 31;
    if (l == 0) ws[w] = v;
    __syncthreads();
    if (threadIdx.x == 0) v = ws[0] + ws[1] + ws[2] + ws[3];
    return v;  // valid on thread 0
}

// final scalar reduction over all 320 partials (block-uniform call, 128 thr)
__device__ __forceinline__ void finalize(float* out) {
    double acc = (double)g_ps[threadIdx.x] + (double)g_ps[threadIdx.x + 128];
    if (threadIdx.x < 64) acc += (double)g_pm[threadIdx.x];
    #pragma unroll
    for (int o = 16; o; o >>= 1) acc += __shfl_xor_sync(0xFFFFFFFFu, acc, o);
    __shared__ double wd[4];
    if ((threadIdx.x & 31) == 0) wd[threadIdx.x >> 5] = acc;
    __syncthreads();
    if (threadIdx.x == 0) out[0] = (float)(wd[0] + wd[1] + wd[2] + wd[3]);
}

// ---------------------------------------------------------------------------
// Single fused kernel, 2 queries/thread, 256-pt tiles (R11 structure,
// main loops unrolled 4x to cut loop overhead / deepen LDS batching).
//   blocks [0, 1024):    skel: 256 m's vs one 256-pt N-split (16 splits).
//                        Last split-block per (b,mchunk) merges + cd2/normals.
//   blocks [1024, 2048): shape: 256 n's vs one 256-pt M-quarter (4 quarters).
//                        Last quarter-block per (b,nchunk) combines -> cd1.
// grid = 2048, block = 128
// ---------------------------------------------------------------------------
__global__ void __launch_bounds__(128) k_all(const float* __restrict__ shape,
                                             const float* __restrict__ skel,
                                             const float* __restrict__ nori,
                                             float* __restrict__ out) {
    __shared__ __align__(16) float sx[256];
    __shared__ __align__(16) float sy[256];
    __shared__ __align__(16) float sz[256];
    __shared__ __align__(16) float sw[256];
    __shared__ __align__(16) float4 s4[256];   // AoS shadow for rescans
    __shared__ bool doFin, lastUnit;

    const int bid = blockIdx.x;
    const int tid = threadIdx.x;

    if (bid < 1024) {
        // ================= skel part (2 m-queries per thread) ================
        const int b      = bid >> 6;        // 16
        const int r      = bid & 63;
        const int split  = r & 15;          // 16
        const int mchunk = r >> 4;          // 4
        const int nbase  = split * NTS;
        const int grp    = b * 4 + mchunk;

        for (int i = tid; i < NTS; i += 128) {
            const float* p = shape + ((size_t)(b * NN + nbase + i)) * 6;
            float X = p[0], Y = p[1], Z = p[2];
            float W = X * X + Y * Y + Z * Z;
            sx[i] = X; sy[i] = Y; sz[i] = Z; sw[i] = W;
            s4[i] = make_float4(X, Y, Z, W);
        }
        __syncthreads();

        const int mbase = mchunk * 256 + tid;
        float fxq[2], fyq[2], fzq[2], ppq[2];
        u64 m2x[2], m2y[2], m2z[2];
        float c[2][8];
        #pragma unroll
        for (int qi = 0; qi < 2; qi++) {
            const int m = mbase + qi * 128;
            const float* s = skel + ((size_t)(b * MM + m)) * 3;
            float qx = s[0], qy = s[1], qz = s[2];
            ppq[qi] = qx * qx + qy * qy + qz * qz;
            fxq[qi] = -2.0f * qx; fyq[qi] = -2.0f * qy; fzq[qi] = -2.0f * qz;
            m2x[qi] = pk2(fxq[qi], fxq[qi]);
            m2y[qi] = pk2(fyq[qi], fyq[qi]);
            m2z[qi] = pk2(fzq[qi], fzq[qi]);
            #pragma unroll
            for (int i = 0; i < 8; i++) c[qi][i] = 1e30f;
        }

        const ulonglong2* x2 = (const ulonglong2*)sx;
        const ulonglong2* y2 = (const ulonglong2*)sy;
        const ulonglong2* z2 = (const ulonglong2*)sz;
        const ulonglong2* w2 = (const ulonglong2*)sw;

        // chains track FLOAT minima of t = w - 2 p.s per mod-8 class;
        // pp is a per-query constant, folded in after the loop.
        #pragma unroll 4
        for (int j = 0; j < NTS; j += 8) {
            const int g = j >> 2;
            ulonglong2 xa = x2[g], xb = x2[g + 1];
            ulonglong2 ya = y2[g], yb = y2[g + 1];
            ulonglong2 za = z2[g], zb = z2[g + 1];
            ulonglong2 wa = w2[g], wb = w2[g + 1];

            #pragma unroll
            for (int qi = 0; qi < 2; qi++) {
                u64 q0 = fmx2(xa.x, m2x[qi], fmx2(ya.x, m2y[qi], fmx2(za.x, m2z[qi], wa.x)));
                u64 q1 = fmx2(xa.y, m2x[qi], fmx2(ya.y, m2y[qi], fmx2(za.y, m2z[qi], wa.y)));
                u64 q2 = fmx2(xb.x, m2x[qi], fmx2(yb.x, m2y[qi], fmx2(zb.x, m2z[qi], wb.x)));
                u64 q3 = fmx2(xb.y, m2x[qi], fmx2(yb.y, m2y[qi], fmx2(zb.y, m2z[qi], wb.y)));

                float f0, f1, f2, f3, f4, f5, f6, f7;
                upkf(q0, f0, f1);
                upkf(q1, f2, f3);
                upkf(q2, f4, f5);
                upkf(q3, f6, f7);
                c[qi][0] = fminf(c[qi][0], f0);
                c[qi][1] = fminf(c[qi][1], f1);
                c[qi][2] = fminf(c[qi][2], f2);
                c[qi][3] = fminf(c[qi][3], f3);
                c[qi][4] = fminf(c[qi][4], f4);
                c[qi][5] = fminf(c[qi][5], f5);
                c[qi][6] = fminf(c[qi][6], f6);
                c[qi][7] = fminf(c[qi][7], f7);
            }
        }

        #pragma unroll
        for (int qi = 0; qi < 2; qi++) {
            // top-2 float values over the 8 chain minima
            float t1v = 1e30f, t2v = 1e30f;
            #pragma unroll
            for (int i = 0; i < 8; i++) upd2f(t1v, t2v, c[qi][i]);
            const int t1b = __float_as_int(t1v);
            const int t2b = __float_as_int(t2v);

            // cc1 = lowest chain attaining t1; cc2 = lowest other chain at t2
            int cc1 = 7;
            #pragma unroll
            for (int k = 6; k >= 0; k--) if (__float_as_int(c[qi][k]) == t1b) cc1 = k;
            int cc2 = (cc1 == 0) ? 1 : 0;
            #pragma unroll
            for (int k = 7; k >= 0; k--) if (__float_as_int(c[qi][k]) == t2b && k != cc1) cc2 = k;

            const float fx = fxq[qi], fy = fyq[qi], fz = fzq[qi], pp = ppq[qi];

            // rescan chain cc1 (32 pts): exact quantized top-2 with indices
            // (identical scalar FMA sequence -> bit-identical values)
            unsigned k1c = ~0u, k2c = ~0u;
            #pragma unroll 4
            for (int j = cc1; j < NTS; j += 8) {
                float4 q = s4[j];
                float tv = fmaf(q.x, fx, fmaf(q.y, fy, fmaf(q.z, fz, q.w)));
                float d2 = tv + pp;
                unsigned u = __float_as_uint(d2);
                upd2(k1c, k2c, (u & KEY_MASK) | (unsigned)j);
            }

            // rescan chain cc2 (32 pts): lowest index whose t matches t2v bits
            unsigned idx2x = IDX_MASK;
            #pragma unroll 4
            for (int j = cc2; j < NTS; j += 8) {
                float4 q = s4[j];
                float tv = fmaf(q.x, fx, fmaf(q.y, fy, fmaf(q.z, fz, q.w)));
                if (__float_as_int(tv) == t2b) idx2x = min(idx2x, (unsigned)j);
            }
            float d2x = t2v + pp;
            unsigned kx = (__float_as_uint(d2x) & KEY_MASK) | idx2x;
            unsigned k2 = min(k2c, kx);

            const int m = mbase + qi * 128;
            g_pk[(b * MM + m) * NSPLIT + split] = make_uint2(k1c, k2);
        }
        __syncthreads();
        if (tid == 0) {
            __threadfence();
            doFin = (atomicInc(&g_gc[grp], 15u) == 15u);
        }
        __syncthreads();

        if (doFin) {
            // ---- merge the 16 splits for this (b, mchunk): 256 m's ----
            float vsum = 0.0f;
            const uint4* pk4 = (const uint4*)g_pk;   // 8 uint4 per m
            #pragma unroll
            for (int qi = 0; qi < 2; qi++) {
                const int t = b * MM + mchunk * 256 + tid + qi * 128;
                float d1 = 1e30f, d2v = 1e30f;
                int n1 = 0, n2 = 0;
                #pragma unroll
                for (int q = 0; q < 8; q++) {
                    uint4 kk = pk4[t * 8 + q];
                    unsigned keys[4] = { kk.x, kk.y, kk.z, kk.w };
                    #pragma unroll
                    for (int i = 0; i < 4; i++) {
                        const int sp = q * 2 + (i >> 1);
                        unsigned key = keys[i];
                        float df = __uint_as_float(key & KEY_MASK);
                        int   nn = (int)(key & IDX_MASK) + sp * NTS;
                        if (df < d1)       { d2v = d1; n2 = n1; d1 = df; n1 = nn; }
                        else if (df < d2v) { d2v = df; n2 = nn; }
                    }
                }

                float cd = sqrtf(fmaxf(d1, 1e-12f));

                const float* nr = nori + (size_t)t * 3;
                const float* f1 = shape + ((size_t)(b * NN + n1)) * 6 + 3;
                const float* f2 = shape + ((size_t)(b * NN + n2)) * 6 + 3;
                float dot1 = nr[0] * f1[0] + nr[1] * f1[1] + nr[2] * f1[2];
                float dot2 = nr[0] * f2[0] + nr[1] * f2[1] + nr[2] * f2[2];

                vsum += 1e-4f * cd + (0.001f / (float)BB) * 0.5f * (fabsf(dot1) + fabsf(dot2));
            }
            float bsum = blockSum128(vsum);

            if (tid == 0) {
                g_pm[grp] = bsum;
                __threadfence();
                lastUnit = (atomicInc(&g_cnt, 319u) == 319u);
            }
            __syncthreads();
            if (lastUnit) finalize(out);
        }
    } else {
        // ================= shape part (cd1, 2 n-queries, quarter-M tiles) ====
        const int sb      = bid - 1024;
        const int b       = sb >> 6;        // 16
        const int r2      = sb & 63;
        const int nchunk  = r2 >> 2;        // 16
        const int quarter = r2 & 3;         // 4
        const int mbase   = quarter * MTS;
        const int grp     = b * 16 + nchunk;

        for (int i = tid; i < MTS; i += 128) {
            const float* s = skel + ((size_t)(b * MM + mbase + i)) * 3;
            float X = s[0], Y = s[1], Z = s[2];
            sx[i] = X; sy[i] = Y; sz[i] = Z;
            sw[i] = X * X + Y * Y + Z * Z;
        }
        __syncthreads();

        u64 m2x[2], m2y[2], m2z[2];
        #pragma unroll
        for (int qi = 0; qi < 2; qi++) {
            const int n = nchunk * 256 + tid + qi * 128;
            const float* p = shape + ((size_t)(b * NN + n)) * 6;
            float px = p[0], py = p[1], pz = p[2];
            m2x[qi] = pk2(-2.0f * px, -2.0f * px);
            m2y[qi] = pk2(-2.0f * py, -2.0f * py);
            m2z[qi] = pk2(-2.0f * pz, -2.0f * pz);
        }

        float mn[2][8];
        #pragma unroll
        for (int qi = 0; qi < 2; qi++)
            #pragma unroll
            for (int i = 0; i < 8; i++) mn[qi][i] = 1e30f;

        const ulonglong2* x2 = (const ulonglong2*)sx;
        const ulonglong2* y2 = (const ulonglong2*)sy;
        const ulonglong2* z2 = (const ulonglong2*)sz;
        const ulonglong2* w2 = (const ulonglong2*)sw;

        #pragma unroll 4
        for (int j = 0; j < MTS; j += 8) {
            const int g = j >> 2;
            ulonglong2 xa = x2[g], xb = x2[g + 1];
            ulonglong2 ya = y2[g], yb = y2[g + 1];
            ulonglong2 za = z2[g], zb = z2[g + 1];
            ulonglong2 wa = w2[g], wb = w2[g + 1];

            #pragma unroll
            for (int qi = 0; qi < 2; qi++) {
                u64 t0 = fmx2(xa.x, m2x[qi], fmx2(ya.x, m2y[qi], fmx2(za.x, m2z[qi], wa.x)));
                u64 t1 = fmx2(xa.y, m2x[qi], fmx2(ya.y, m2y[qi], fmx2(za.y, m2z[qi], wa.y)));
                u64 t2 = fmx2(xb.x, m2x[qi], fmx2(yb.x, m2y[qi], fmx2(zb.x, m2z[qi], wb.x)));
                u64 t3 = fmx2(xb.y, m2x[qi], fmx2(yb.y, m2y[qi], fmx2(zb.y, m2z[qi], wb.y)));

                float f0, f1, f2, f3, f4, f5, f6, f7;
                upkf(t0, f0, f1);
                upkf(t1, f2, f3);
                upkf(t2, f4, f5);
                upkf(t3, f6, f7);
                mn[qi][0] = fminf(mn[qi][0], f0);
                mn[qi][1] = fminf(mn[qi][1], f1);
                mn[qi][2] = fminf(mn[qi][2], f2);
                mn[qi][3] = fminf(mn[qi][3], f3);
                mn[qi][4] = fminf(mn[qi][4], f4);
                mn[qi][5] = fminf(mn[qi][5], f5);
                mn[qi][6] = fminf(mn[qi][6], f6);
                mn[qi][7] = fminf(mn[qi][7], f7);
            }
        }

        #pragma unroll
        for (int qi = 0; qi < 2; qi++) {
            float tmin = fminf(fminf(fminf(mn[qi][0], mn[qi][1]), fminf(mn[qi][2], mn[qi][3])),
                               fminf(fminf(mn[qi][4], mn[qi][5]), fminf(mn[qi][6], mn[qi][7])));
            g_sm[(grp * MSPLIT + quarter) * 256 + tid + qi * 128] = tmin;
        }
        __syncthreads();
        if (tid == 0) {
            __threadfence();
            doFin = (atomicInc(&g_sc[grp], 3u) == 3u);
        }
        __syncthreads();

        if (doFin) {
            float vsum = 0.0f;
            #pragma unroll
            for (int qi = 0; qi < 2; qi++) {
                const int idx = tid + qi * 128;
                float t0 = g_sm[(grp * MSPLIT + 0) * 256 + idx];
                float t1 = g_sm[(grp * MSPLIT + 1) * 256 + idx];
                float t2 = g_sm[(grp * MSPLIT + 2) * 256 + idx];
                float t3 = g_sm[(grp * MSPLIT + 3) * 256 + idx];
                float tm = fminf(fminf(t0, t1), fminf(t2, t3));
                const int n = nchunk * 256 + idx;
                const float* pq = shape + ((size_t)(b * NN + n)) * 6;
                float ppx = pq[0], ppy = pq[1], ppz = pq[2];
                float ppv = ppx * ppx + ppy * ppy + ppz * ppz;
                float dmin = ppv + tm;
                vsum += 1e-4f * sqrtf(fmaxf(dmin, 1e-12f));
            }

            float bsum = blockSum128(vsum);
            if (tid == 0) {
                g_ps[grp] = bsum;
                __threadfence();
                lastUnit = (atomicInc(&g_cnt, 319u) == 319u);
            }
            __syncthreads();
            if (lastUnit) finalize(out);
        }
    }
}

extern "C" void kernel_launch(void* const* d_in, const int* in_sizes, int n_in,
                              void* d_out, int out_size) {
    const float* shape = (const float*)d_in[0];  // (B, N, 6)
    const float* skel  = (const float*)d_in[1];  // (B, M, 3)
    const float* nori  = (const float*)d_in[2];  // (B, M, 3)
    float* out = (float*)d_out;

    k_all<<<2048, 128>>>(shape, skel, nori, out);
}

// round 17
// speedup vs baseline: 1.6096x; 1.0653x over previous
#include <cuda_runtime.h>
#include <math.h>

#define BB 16
#define NN 4096
#define MM 1024
#define NSPLIT 16
#define NTS (NN / NSPLIT)   // 256: skel tile size
#define MSPLIT 4
#define MTS (MM / MSPLIT)   // 256: shape tile size

#define KEY_MASK 0xFFFFFC00u
#define IDX_MASK 0x000003FFu

typedef unsigned long long u64;

// scratch (static device globals: no allocation allowed)
__device__ uint2        g_pk[BB * MM * NSPLIT];      // per-split (best, second) keys
__device__ float        g_sm[128 * MSPLIT * 512];    // shape quarter-tile partial tmins
__device__ float        g_ps[128];                   // shape-group partials (16*8)
__device__ float        g_pm[32];                    // merge-group partials (16*2)
__device__ unsigned int g_gc[32];                    // skel merge counters (wrap 15)
__device__ unsigned int g_sc[128];                   // shape combine counters (wrap 3)
__device__ unsigned int g_cnt = 0;                   // global counter (160 units)

// ---- packed f32x2 helpers ----
__device__ __forceinline__ u64 fmx2(u64 a, u64 b, u64 c) {
    u64 r; asm("fma.rn.f32x2 %0,%1,%2,%3;" : "=l"(r) : "l"(a), "l"(b), "l"(c)); return r;
}
__device__ __forceinline__ u64 pk2(float a, float b) {
    u64 r; asm("mov.b64 %0,{%1,%2};" : "=l"(r) : "f"(a), "f"(b)); return r;
}
__device__ __forceinline__ void upkf(u64 v, float& a, float& b) {
    asm("mov.b64 {%0,%1},%2;" : "=f"(a), "=f"(b) : "l"(v));
}

// branch-free top-2 update on packed keys (positive-float uint ordering)
__device__ __forceinline__ void upd2(unsigned& b1, unsigned& b2, unsigned k) {
    unsigned mx = max(k, b1);
    b2 = min(b2, mx);
    b1 = min(b1, k);
}
// float variant (correct IEEE order incl. negatives; no NaNs here)
__device__ __forceinline__ void upd2f(float& b1, float& b2, float k) {
    float mx = fmaxf(k, b1);
    b2 = fminf(b2, mx);
    b1 = fminf(b1, k);
}

__device__ __forceinline__ float blockSum256(float v) {
    #pragma unroll
    for (int o = 16; o; o >>= 1) v += __shfl_xor_sync(0xFFFFFFFFu, v, o);
    __shared__ float ws[8];
    int w = threadIdx.x >> 5, l = threadIdx.x & 31;
    if (l == 0) ws[w] = v;
    __syncthreads();
    if (threadIdx.x == 0) {
        float s = 0.0f;
        #pragma unroll
        for (int i = 0; i < 8; i++) s += ws[i];
        v = s;
    }
    return v;  // valid on thread 0
}

// final scalar reduction over all 160 partials (block-uniform call, 256 thr)
__device__ __forceinline__ void finalize(float* out) {
    double acc = 0.0;
    if (threadIdx.x < 128) acc += (double)g_ps[threadIdx.x];
    if (threadIdx.x < 32)  acc += (double)g_pm[threadIdx.x];
    #pragma unroll
    for (int o = 16; o; o >>= 1) acc += __shfl_xor_sync(0xFFFFFFFFu, acc, o);
    __shared__ double wd[8];
    if ((threadIdx.x & 31) == 0) wd[threadIdx.x >> 5] = acc;
    __syncthreads();
    if (threadIdx.x == 0) {
        double s = 0.0;
        #pragma unroll
        for (int i = 0; i < 8; i++) s += wd[i];
        out[0] = (float)s;
    }
}

// ---------------------------------------------------------------------------
// Single fused kernel, 2 queries/thread, 256-pt tiles, 256-thread blocks.
//   blocks [0, 512):   skel: 512 m's vs one 256-pt N-split (16 splits).
//                      Last split-block per (b,mchunk) merges + cd2/normals.
//   blocks [512,1024): shape: 512 n's vs one 256-pt M-quarter (4 quarters).
//                      Last quarter-block per (b,nchunk) combines -> cd1.
// grid = 1024, block = 256
// ---------------------------------------------------------------------------
__global__ void __launch_bounds__(256) k_all(const float* __restrict__ shape,
                                             const float* __restrict__ skel,
                                             const float* __restrict__ nori,
                                             float* __restrict__ out) {
    __shared__ __align__(16) float sx[256];
    __shared__ __align__(16) float sy[256];
    __shared__ __align__(16) float sz[256];
    __shared__ __align__(16) float sw[256];
    __shared__ __align__(16) float4 s4[256];   // AoS shadow for rescans
    __shared__ bool doFin, lastUnit;

    const int bid = blockIdx.x;
    const int tid = threadIdx.x;

    if (bid < 512) {
        // ================= skel part (2 m-queries per thread) ================
        const int b      = bid >> 5;        // 16
        const int r      = bid & 31;
        const int split  = r & 15;          // 16
        const int mchunk = r >> 4;          // 2
        const int nbase  = split * NTS;
        const int grp    = b * 2 + mchunk;

        if (tid < NTS) {
            const float* p = shape + ((size_t)(b * NN + nbase + tid)) * 6;
            float X = p[0], Y = p[1], Z = p[2];
            float W = X * X + Y * Y + Z * Z;
            sx[tid] = X; sy[tid] = Y; sz[tid] = Z; sw[tid] = W;
            s4[tid] = make_float4(X, Y, Z, W);
        }
        __syncthreads();

        const int mbase = mchunk * 512 + tid;
        float ppq[2];
        u64 m2x[2], m2y[2], m2z[2];
        float c[2][8];
        #pragma unroll
        for (int qi = 0; qi < 2; qi++) {
            const int m = mbase + qi * 256;
            const float* s = skel + ((size_t)(b * MM + m)) * 3;
            float qx = s[0], qy = s[1], qz = s[2];
            ppq[qi] = qx * qx + qy * qy + qz * qz;
            m2x[qi] = pk2(-2.0f * qx, -2.0f * qx);
            m2y[qi] = pk2(-2.0f * qy, -2.0f * qy);
            m2z[qi] = pk2(-2.0f * qz, -2.0f * qz);
            #pragma unroll
            for (int i = 0; i < 8; i++) c[qi][i] = 1e30f;
        }

        const ulonglong2* x2 = (const ulonglong2*)sx;
        const ulonglong2* y2 = (const ulonglong2*)sy;
        const ulonglong2* z2 = (const ulonglong2*)sz;
        const ulonglong2* w2 = (const ulonglong2*)sw;

        // chains track FLOAT minima of t = w - 2 p.s per mod-8 class;
        // pp is a per-query constant, folded in after the loop.
        #pragma unroll 4
        for (int j = 0; j < NTS; j += 8) {
            const int g = j >> 2;
            ulonglong2 xa = x2[g], xb = x2[g + 1];
            ulonglong2 ya = y2[g], yb = y2[g + 1];
            ulonglong2 za = z2[g], zb = z2[g + 1];
            ulonglong2 wa = w2[g], wb = w2[g + 1];

            #pragma unroll
            for (int qi = 0; qi < 2; qi++) {
                u64 q0 = fmx2(xa.x, m2x[qi], fmx2(ya.x, m2y[qi], fmx2(za.x, m2z[qi], wa.x)));
                u64 q1 = fmx2(xa.y, m2x[qi], fmx2(ya.y, m2y[qi], fmx2(za.y, m2z[qi], wa.y)));
                u64 q2 = fmx2(xb.x, m2x[qi], fmx2(yb.x, m2y[qi], fmx2(zb.x, m2z[qi], wb.x)));
                u64 q3 = fmx2(xb.y, m2x[qi], fmx2(yb.y, m2y[qi], fmx2(zb.y, m2z[qi], wb.y)));

                float f0, f1, f2, f3, f4, f5, f6, f7;
                upkf(q0, f0, f1);
                upkf(q1, f2, f3);
                upkf(q2, f4, f5);
                upkf(q3, f6, f7);
                c[qi][0] = fminf(c[qi][0], f0);
                c[qi][1] = fminf(c[qi][1], f1);
                c[qi][2] = fminf(c[qi][2], f2);
                c[qi][3] = fminf(c[qi][3], f3);
                c[qi][4] = fminf(c[qi][4], f4);
                c[qi][5] = fminf(c[qi][5], f5);
                c[qi][6] = fminf(c[qi][6], f6);
                c[qi][7] = fminf(c[qi][7], f7);
            }
        }

        #pragma unroll
        for (int qi = 0; qi < 2; qi++) {
            // top-2 float values over the 8 chain minima
            float t1v = 1e30f, t2v = 1e30f;
            #pragma unroll
            for (int i = 0; i < 8; i++) upd2f(t1v, t2v, c[qi][i]);
            const int t1b = __float_as_int(t1v);
            const int t2b = __float_as_int(t2v);

            // cc1 = lowest chain attaining t1; cc2 = lowest other chain at t2
            int cc1 = 7;
            #pragma unroll
            for (int k = 6; k >= 0; k--) if (__float_as_int(c[qi][k]) == t1b) cc1 = k;
            int cc2 = (cc1 == 0) ? 1 : 0;
            #pragma unroll
            for (int k = 7; k >= 0; k--) if (__float_as_int(c[qi][k]) == t2b && k != cc1) cc2 = k;

            const float pp = ppq[qi];
            float fx, fy, fz, dum;
            upkf(m2x[qi], fx, dum);
            upkf(m2y[qi], fy, dum);
            upkf(m2z[qi], fz, dum);

            // rescan chain cc1 (32 pts): exact quantized top-2 with indices
            // (identical scalar FMA sequence -> bit-identical values)
            unsigned k1c = ~0u, k2c = ~0u;
            #pragma unroll 4
            for (int j = cc1; j < NTS; j += 8) {
                float4 q = s4[j];
                float tv = fmaf(q.x, fx, fmaf(q.y, fy, fmaf(q.z, fz, q.w)));
                float d2 = tv + pp;
                unsigned u = __float_as_uint(d2);
                upd2(k1c, k2c, (u & KEY_MASK) | (unsigned)j);
            }

            // rescan chain cc2 (32 pts): lowest index whose t matches t2v bits
            unsigned idx2x = IDX_MASK;
            #pragma unroll 4
            for (int j = cc2; j < NTS; j += 8) {
                float4 q = s4[j];
                float tv = fmaf(q.x, fx, fmaf(q.y, fy, fmaf(q.z, fz, q.w)));
                if (__float_as_int(tv) == t2b) idx2x = min(idx2x, (unsigned)j);
            }
            float d2x = t2v + pp;
            unsigned kx = (__float_as_uint(d2x) & KEY_MASK) | idx2x;
            unsigned k2 = min(k2c, kx);

            const int m = mbase + qi * 256;
            g_pk[(b * MM + m) * NSPLIT + split] = make_uint2(k1c, k2);
        }
        __syncthreads();
        if (tid == 0) {
            __threadfence();
            doFin = (atomicInc(&g_gc[grp], 15u) == 15u);
        }
        __syncthreads();

        if (doFin) {
            // ---- merge the 16 splits for this (b, mchunk): 512 m's ----
            float vsum = 0.0f;
            const uint4* pk4 = (const uint4*)g_pk;   // 8 uint4 per m
            #pragma unroll
            for (int qi = 0; qi < 2; qi++) {
                const int t = b * MM + mchunk * 512 + tid + qi * 256;
                float d1 = 1e30f, d2v = 1e30f;
                int n1 = 0, n2 = 0;
                #pragma unroll
                for (int q = 0; q < 8; q++) {
                    uint4 kk = pk4[t * 8 + q];
                    unsigned keys[4] = { kk.x, kk.y, kk.z, kk.w };
                    #pragma unroll
                    for (int i = 0; i < 4; i++) {
                        const int sp = q * 2 + (i >> 1);
                        unsigned key = keys[i];
                        float df = __uint_as_float(key & KEY_MASK);
                        int   nn = (int)(key & IDX_MASK) + sp * NTS;
                        if (df < d1)       { d2v = d1; n2 = n1; d1 = df; n1 = nn; }
                        else if (df < d2v) { d2v = df; n2 = nn; }
                    }
                }

                float cd = sqrtf(fmaxf(d1, 1e-12f));

                const float* nr = nori + (size_t)t * 3;
                const float* f1 = shape + ((size_t)(b * NN + n1)) * 6 + 3;
                const float* f2 = shape + ((size_t)(b * NN + n2)) * 6 + 3;
                float dot1 = nr[0] * f1[0] + nr[1] * f1[1] + nr[2] * f1[2];
                float dot2 = nr[0] * f2[0] + nr[1] * f2[1] + nr[2] * f2[2];

                vsum += 1e-4f * cd + (0.001f / (float)BB) * 0.5f * (fabsf(dot1) + fabsf(dot2));
            }
            float bsum = blockSum256(vsum);

            if (tid == 0) {
                g_pm[grp] = bsum;
                __threadfence();
                lastUnit = (atomicInc(&g_cnt, 159u) == 159u);
            }
            __syncthreads();
            if (lastUnit) finalize(out);
        }
    } else {
        // ================= shape part (cd1, 2 n-queries, quarter-M tiles) ====
        const int sb      = bid - 512;
        const int b       = sb >> 5;        // 16
        const int r2      = sb & 31;
        const int nchunk  = r2 >> 2;        // 8
        const int quarter = r2 & 3;         // 4
        const int mbase   = quarter * MTS;
        const int grp     = b * 8 + nchunk;

        if (tid < MTS) {
            const float* s = skel + ((size_t)(b * MM + mbase + tid)) * 3;
            float X = s[0], Y = s[1], Z = s[2];
            sx[tid] = X; sy[tid] = Y; sz[tid] = Z;
            sw[tid] = X * X + Y * Y + Z * Z;
        }
        __syncthreads();

        u64 m2x[2], m2y[2], m2z[2];
        #pragma unroll
        for (int qi = 0; qi < 2; qi++) {
            const int n = nchunk * 512 + tid + qi * 256;
            const float* p = shape + ((size_t)(b * NN + n)) * 6;
            float px = p[0], py = p[1], pz = p[2];
            m2x[qi] = pk2(-2.0f * px, -2.0f * px);
            m2y[qi] = pk2(-2.0f * py, -2.0f * py);
            m2z[qi] = pk2(-2.0f * pz, -2.0f * pz);
        }

        float mn[2][8];
        #pragma unroll
        for (int qi = 0; qi < 2; qi++)
            #pragma unroll
            for (int i = 0; i < 8; i++) mn[qi][i] = 1e30f;

        const ulonglong2* x2 = (const ulonglong2*)sx;
        const ulonglong2* y2 = (const ulonglong2*)sy;
        const ulonglong2* z2 = (const ulonglong2*)sz;
        const ulonglong2* w2 = (const ulonglong2*)sw;

        #pragma unroll 4
        for (int j = 0; j < MTS; j += 8) {
            const int g = j >> 2;
            ulonglong2 xa = x2[g], xb = x2[g + 1];
            ulonglong2 ya = y2[g], yb = y2[g + 1];
            ulonglong2 za = z2[g], zb = z2[g + 1];
            ulonglong2 wa = w2[g], wb = w2[g + 1];

            #pragma unroll
            for (int qi = 0; qi < 2; qi++) {
                u64 t0 = fmx2(xa.x, m2x[qi], fmx2(ya.x, m2y[qi], fmx2(za.x, m2z[qi], wa.x)));
                u64 t1 = fmx2(xa.y, m2x[qi], fmx2(ya.y, m2y[qi], fmx2(za.y, m2z[qi], wa.y)));
                u64 t2 = fmx2(xb.x, m2x[qi], fmx2(yb.x, m2y[qi], fmx2(zb.x, m2z[qi], wb.x)));
                u64 t3 = fmx2(xb.y, m2x[qi], fmx2(yb.y, m2y[qi], fmx2(zb.y, m2z[qi], wb.y)));

                float f0, f1, f2, f3, f4, f5, f6, f7;
                upkf(t0, f0, f1);
                upkf(t1, f2, f3);
                upkf(t2, f4, f5);
                upkf(t3, f6, f7);
                mn[qi][0] = fminf(mn[qi][0], f0);
                mn[qi][1] = fminf(mn[qi][1], f1);
                mn[qi][2] = fminf(mn[qi][2], f2);
                mn[qi][3] = fminf(mn[qi][3], f3);
                mn[qi][4] = fminf(mn[qi][4], f4);
                mn[qi][5] = fminf(mn[qi][5], f5);
                mn[qi][6] = fminf(mn[qi][6], f6);
                mn[qi][7] = fminf(mn[qi][7], f7);
            }
        }

        #pragma unroll
        for (int qi = 0; qi < 2; qi++) {
            float tmin = fminf(fminf(fminf(mn[qi][0], mn[qi][1]), fminf(mn[qi][2], mn[qi][3])),
                               fminf(fminf(mn[qi][4], mn[qi][5]), fminf(mn[qi][6], mn[qi][7])));
            g_sm[(grp * MSPLIT + quarter) * 512 + tid + qi * 256] = tmin;
        }
        __syncthreads();
        if (tid == 0) {
            __threadfence();
            doFin = (atomicInc(&g_sc[grp], 3u) == 3u);
        }
        __syncthreads();

        if (doFin) {
            float vsum = 0.0f;
            #pragma unroll
            for (int qi = 0; qi < 2; qi++) {
                const int idx = tid + qi * 256;
                float t0 = g_sm[(grp * MSPLIT + 0) * 512 + idx];
                float t1 = g_sm[(grp * MSPLIT + 1) * 512 + idx];
                float t2 = g_sm[(grp * MSPLIT + 2) * 512 + idx];
                float t3 = g_sm[(grp * MSPLIT + 3) * 512 + idx];
                float tm = fminf(fminf(t0, t1), fminf(t2, t3));
                const int n = nchunk * 512 + idx;
                const float* pq = shape + ((size_t)(b * NN + n)) * 6;
                float ppx = pq[0], ppy = pq[1], ppz = pq[2];
                float ppv = ppx * ppx + ppy * ppy + ppz * ppz;
                float dmin = ppv + tm;
                vsum += 1e-4f * sqrtf(fmaxf(dmin, 1e-12f));
            }

            float bsum = blockSum256(vsum);
            if (tid == 0) {
                g_ps[grp] = bsum;
                __threadfence();
                lastUnit = (atomicInc(&g_cnt, 159u) == 159u);
            }
            __syncthreads();
            if (lastUnit) finalize(out);
        }
    }
}

extern "C" void kernel_launch(void* const* d_in, const int* in_sizes, int n_in,
                              void* d_out, int out_size) {
    const float* shape = (const float*)d_in[0];  // (B, N, 6)
    const float* skel  = (const float*)d_in[1];  // (B, M, 3)
    const float* nori  = (const float*)d_in[2];  // (B, M, 3)
    float* out = (float*)d_out;

    k_all<<<1024, 256>>>(shape, skel, nori, out);
}